// round 10
// baseline (speedup 1.0000x reference)
#include <cuda_runtime.h>
#include <cstdint>
#include <cstddef>

typedef unsigned long long u64;

#define T_LEN 1024
#define HID   256
#define BGN   4        // batch groups
#define HGN   32       // hidden groups (CTAs per batch group)
#define BC    32       // batch rows per CTA
#define UC    8        // hidden units per CTA
#define ROWP  260      // padded row stride (floats): 1040B -> conflict-free LDS.128
#define GOFF  (UC*ROWP)       // gate stride inside a W slice
#define NTHR  256

#define SMEM_FLOATS ((4*3*UC + 3*BC) * ROWP)     // 4 W slices (24 rows) + 3 tiles (32 rows)
#define SMEM_BYTES  (SMEM_FLOATS * 4)

// persistent device state (zero-initialized .bss; allocation-free)
__device__ u64   g_flag[BGN * HGN];
__device__ float g_h0[128 * HID];
__device__ float g_h1[128 * HID];

// ---------------------------------------------------------------------------
__device__ __forceinline__ void ffma2(u64& a, u64 b, u64 c) {
    asm("fma.rn.f32x2 %0, %1, %2, %0;" : "+l"(a) : "l"(b), "l"(c));
}
__device__ __forceinline__ float us(u64 v) {
    float lo, hi;
    asm("mov.b64 {%0,%1}, %2;" : "=f"(lo), "=f"(hi) : "l"(v));
    return lo + hi;
}
__device__ __forceinline__ u64 ldacq(const u64* p) {
    u64 v;
    asm volatile("ld.acquire.gpu.u64 %0, [%1];" : "=l"(v) : "l"(p) : "memory");
    return v;
}
__device__ __forceinline__ void strel(u64* p, u64 v) {
    asm volatile("st.release.gpu.u64 [%0], %1;" :: "l"(p), "l"(v) : "memory");
}
__device__ __forceinline__ float sigm(float v) { return 1.0f / (1.0f + __expf(-v)); }
__device__ __forceinline__ float tanh_(float v) {
    float e = __expf(-2.0f * fabsf(v));
    return copysignf((1.0f - e) / (1.0f + e), v);
}

// 3-gate GRU cell dot products for one (batch,unit) pair.
// pA: input vector (x or h0), pB: hidden vector; wA/wB: this unit's gate-0 row.
__device__ __forceinline__ float gru_cell(
    const float* __restrict__ pA, const float* __restrict__ pB,
    const float* __restrict__ wA, const float* __restrict__ wB,
    float br, float bz, float bxn, float bhn, float hold)
{
    u64 ar0 = 0, ar1 = 0, az0 = 0, az1 = 0, nx0 = 0, nx1 = 0, nh0 = 0, nh1 = 0;
#pragma unroll 2
    for (int k = 0; k < 64; ++k) {
        ulonglong2 a  = *(const ulonglong2*)(pA + k * 4);
        ulonglong2 b  = *(const ulonglong2*)(pB + k * 4);
        ulonglong2 ra = *(const ulonglong2*)(wA + k * 4);
        ulonglong2 rb = *(const ulonglong2*)(wB + k * 4);
        ulonglong2 za = *(const ulonglong2*)(wA + GOFF + k * 4);
        ulonglong2 zb = *(const ulonglong2*)(wB + GOFF + k * 4);
        ulonglong2 na = *(const ulonglong2*)(wA + 2 * GOFF + k * 4);
        ulonglong2 nb = *(const ulonglong2*)(wB + 2 * GOFF + k * 4);
        ffma2(ar0, ra.x, a.x); ffma2(ar1, ra.y, a.y);
        ffma2(ar0, rb.x, b.x); ffma2(ar1, rb.y, b.y);
        ffma2(az0, za.x, a.x); ffma2(az1, za.y, a.y);
        ffma2(az0, zb.x, b.x); ffma2(az1, zb.y, b.y);
        ffma2(nx0, na.x, a.x); ffma2(nx1, na.y, a.y);
        ffma2(nh0, nb.x, b.x); ffma2(nh1, nb.y, b.y);
    }
    float r = sigm(us(ar0) + us(ar1) + br);
    float z = sigm(us(az0) + us(az1) + bz);
    float n = tanh_(us(nx0) + us(nx1) + bxn + r * (us(nh0) + us(nh1) + bhn));
    return z * hold + (1.0f - z) * n;
}

__device__ __forceinline__ void fill_w(float* sw, const float* __restrict__ W,
                                       int hg, int tid) {
    for (int i = tid; i < 3 * UC * 64; i += NTHR) {
        int lr = i >> 6, q = i & 63;
        int g = lr >> 3, u = lr & 7;
        float4 v = __ldg((const float4*)(W + (size_t)(g * HID + hg * UC + u) * HID) + q);
        *(float4*)(sw + lr * ROWP + q * 4) = v;
    }
}

__device__ __forceinline__ void load_tile(float* dst, const float* __restrict__ g,
                                          int bg, int tid) {
    int br = tid >> 3, q0 = (tid & 7) * 8;
    const float4* s = (const float4*)(g + (size_t)(bg * BC + br) * HID) + q0;
    float* d = dst + br * ROWP + q0 * 4;
#pragma unroll
    for (int i = 0; i < 8; ++i) *(float4*)(d + i * 4) = __ldcg(s + i);
}

__device__ __forceinline__ void pref_x(float4* xr, const float* __restrict__ x,
                                       int bg, int t, int tid) {
    int br = tid >> 3, q0 = (tid & 7) * 8;
    const float4* s =
        (const float4*)(x + ((size_t)(bg * BC + br) * T_LEN + t) * HID) + q0;
#pragma unroll
    for (int i = 0; i < 8; ++i) xr[i] = __ldcg(s + i);
}

__device__ __forceinline__ void store_x(const float4* xr, float* sx, int tid) {
    int br = tid >> 3, q0 = (tid & 7) * 8;
    float* d = sx + br * ROWP + q0 * 4;
#pragma unroll
    for (int i = 0; i < 8; ++i) *(float4*)(d + i * 4) = xr[i];
}

// ---------------------------------------------------------------------------
__global__ void __launch_bounds__(NTHR, 1)
gru_persistent(const float* __restrict__ x,
               const float* __restrict__ Wx0, const float* __restrict__ bx0,
               const float* __restrict__ Wh0, const float* __restrict__ bh0,
               const float* __restrict__ Wx1, const float* __restrict__ bx1,
               const float* __restrict__ Wh1, const float* __restrict__ bh1,
               const float* __restrict__ Wo,  const float* __restrict__ bo,
               float* __restrict__ out)
{
    extern __shared__ float sm[];
    float* sWx0 = sm;
    float* sWh0 = sWx0 + 3 * UC * ROWP;
    float* sWx1 = sWh0 + 3 * UC * ROWP;
    float* sWh1 = sWx1 + 3 * UC * ROWP;
    float* sx   = sWh1 + 3 * UC * ROWP;
    float* sh0  = sx  + BC * ROWP;
    float* sh1  = sh0 + BC * ROWP;

    const int tid = threadIdx.x;
    const int bg  = blockIdx.x >> 5;      // 0..3
    const int hg  = blockIdx.x & 31;      // 0..31
    const int b   = tid >> 3;             // 0..31 local batch row
    const int u   = tid & 7;              // 0..7  local unit
    const int ug  = hg * UC + u;          // global unit
    const int gb  = bg * BC + b;          // global batch row

    // weights into SMEM (once)
    fill_w(sWx0, Wx0, hg, tid);
    fill_w(sWh0, Wh0, hg, tid);
    fill_w(sWx1, Wx1, hg, tid);
    fill_w(sWh1, Wh1, hg, tid);
    // zero h tiles, load x(t=0)
    for (int i = tid; i < BC * ROWP; i += NTHR) { sh0[i] = 0.0f; sh1[i] = 0.0f; }
    {
        float4 xr[8];
        pref_x(xr, x, bg, 0, tid);
        store_x(xr, sx, tid);
    }
    __syncthreads();

    // biases (r,z folded; n kept split)
    const float br0  = bx0[ug] + bh0[ug];
    const float bz0  = bx0[HID + ug] + bh0[HID + ug];
    const float bxn0 = bx0[2 * HID + ug], bhn0 = bh0[2 * HID + ug];
    const float br1  = bx1[ug] + bh1[ug];
    const float bz1  = bx1[HID + ug] + bh1[HID + ug];
    const float bxn1 = bx1[2 * HID + ug], bhn1 = bh1[2 * HID + ug];

    const float* wxa = sWx0 + u * ROWP;   // gate-0 row of this unit
    const float* wha = sWh0 + u * ROWP;
    const float* wxb = sWx1 + u * ROWP;
    const float* whb = sWh1 + u * ROWP;
    u64* myflag = &g_flag[bg * HGN + hg];
    const u64 base = *myflag;             // equal across bg (all CTAs finish all phases)

    for (int t = 0; t < T_LEN; ++t) {
        // ---- phase A: layer-0 cell ----
        float h0n = gru_cell(sx + b * ROWP, sh0 + b * ROWP, wxa, wha,
                             br0, bz0, bxn0, bhn0, sh0[b * ROWP + ug]);
        g_h0[(size_t)gb * HID + ug] = h0n;
        __threadfence();
        __syncthreads();
        if (tid == 0) strel(myflag, base + (u64)(2 * t + 1));

        float4 xr[8];
        if (t + 1 < T_LEN) pref_x(xr, x, bg, t + 1, tid);   // overlap with spin

        if (tid < HGN) {
            const u64* f = &g_flag[bg * HGN + tid];
            while (ldacq(f) < base + (u64)(2 * t + 1)) __nanosleep(32);
        }
        __syncthreads();
        load_tile(sh0, g_h0, bg, tid);
        __syncthreads();

        // ---- phase B: layer-1 cell (input = fresh h0) ----
        float h1n = gru_cell(sh0 + b * ROWP, sh1 + b * ROWP, wxb, whb,
                             br1, bz1, bxn1, bhn1, sh1[b * ROWP + ug]);
        g_h1[(size_t)gb * HID + ug] = h1n;
        __threadfence();
        __syncthreads();
        if (tid == 0) strel(myflag, base + (u64)(2 * t + 2));

        if (t + 1 < T_LEN) store_x(xr, sx, tid);            // sx free after phase A

        if (tid < HGN) {
            const u64* f = &g_flag[bg * HGN + tid];
            while (ldacq(f) < base + (u64)(2 * t + 2)) __nanosleep(32);
        }
        __syncthreads();
        load_tile(sh1, g_h1, bg, tid);
        __syncthreads();
    }

    // ---- output projection: out = h1 @ Wo.T + bo (hg < 16 covers all 128 cols) ----
    if (hg < 16) {
        const int o = hg * UC + u;
        const ulonglong2* wo = (const ulonglong2*)(Wo + (size_t)o * HID);
        const float* ph = sh1 + b * ROWP;
        u64 a0 = 0, a1 = 0;
#pragma unroll 4
        for (int k = 0; k < 64; ++k) {
            ulonglong2 h = *(const ulonglong2*)(ph + k * 4);
            ulonglong2 w = __ldg(wo + k);
            ffma2(a0, w.x, h.x);
            ffma2(a1, w.y, h.y);
        }
        out[(size_t)gb * 128 + o] = us(a0) + us(a1) + __ldg(bo + o);
    }
}

// ---------------------------------------------------------------------------
extern "C" void kernel_launch(void* const* d_in, const int* in_sizes, int n_in,
                              void* d_out, int out_size) {
    (void)in_sizes; (void)n_in; (void)out_size;
    const float* x   = (const float*)d_in[0];
    const float* Wx0 = (const float*)d_in[1];
    const float* bx0 = (const float*)d_in[2];
    const float* Wh0 = (const float*)d_in[3];
    const float* bh0 = (const float*)d_in[4];
    const float* Wx1 = (const float*)d_in[5];
    const float* bx1 = (const float*)d_in[6];
    const float* Wh1 = (const float*)d_in[7];
    const float* bh1 = (const float*)d_in[8];
    const float* Wo  = (const float*)d_in[9];
    const float* bo  = (const float*)d_in[10];
    float* out = (float*)d_out;

    cudaFuncSetAttribute(gru_persistent,
                         cudaFuncAttributeMaxDynamicSharedMemorySize, SMEM_BYTES);
    gru_persistent<<<BGN * HGN, NTHR, SMEM_BYTES>>>(
        x, Wx0, bx0, Wh0, bh0, Wx1, bx1, Wh1, bh1, Wo, bo, out);
}

// round 11
// speedup vs baseline: 1.5619x; 1.5619x over previous
#include <cuda_runtime.h>
#include <cstdint>
#include <cstddef>

typedef unsigned long long u64;
typedef ulonglong2 ull2;

#define T_LEN 1024
#define HID   256
#define BGN   4        // batch groups
#define HGN   32       // hidden groups (CTAs per batch group)
#define BC    32       // batch rows per CTA
#define UC    8        // hidden units per CTA
#define NTHR  256

#define WSZ   (3*UC*HID)          // one W slice: 24 rows x 256
#define TSZ   (BC*HID)            // one activation tile: 32 rows x 256
#define SMEM_FLOATS (4*WSZ + 3*TSZ)
#define SMEM_BYTES  (SMEM_FLOATS*4)   // 196608 B

// persistent device state (allocation-free)
__device__ u64   g_flag[BGN * HGN];
__device__ float g_h0[128 * HID];
__device__ float g_h1[128 * HID];

// ---------------------------------------------------------------------------
__device__ __forceinline__ void ffma2(u64& a, u64 b, u64 c) {
    asm("fma.rn.f32x2 %0, %1, %2, %0;" : "+l"(a) : "l"(b), "l"(c));
}
__device__ __forceinline__ float us(u64 v) {
    float lo, hi;
    asm("mov.b64 {%0,%1}, %2;" : "=f"(lo), "=f"(hi) : "l"(v));
    return lo + hi;
}
__device__ __forceinline__ u64 ldacq(const u64* p) {
    u64 v;
    asm volatile("ld.acquire.gpu.u64 %0, [%1];" : "=l"(v) : "l"(p) : "memory");
    return v;
}
__device__ __forceinline__ void strel(u64* p, u64 v) {
    asm volatile("st.release.gpu.u64 [%0], %1;" :: "l"(p), "l"(v) : "memory");
}
__device__ __forceinline__ float sigm(float v) { return 1.0f / (1.0f + __expf(-v)); }
__device__ __forceinline__ float tanh_(float v) {
    float e = __expf(-2.0f * fabsf(v));
    return copysignf((1.0f - e) / (1.0f + e), v);
}
__device__ __forceinline__ int swz(int g) { return g ^ ((g >> 3) & 7); }

// ---------------------------------------------------------------------------
// SMEM fill / tile movement (all use the granule swizzle)
// ---------------------------------------------------------------------------
__device__ __forceinline__ void fill_w(float* sw, const float* __restrict__ W,
                                       int hg, int tid) {
    for (int i = tid; i < 3 * UC * 64; i += NTHR) {
        int lr = i >> 6, q = i & 63;
        int g = lr >> 3, u = lr & 7;
        float4 v = __ldg((const float4*)(W + (size_t)(g * HID + hg * UC + u) * HID) + q);
        *(float4*)(sw + lr * HID + swz(q) * 4) = v;
    }
}

__device__ __forceinline__ void load_tile(float* dst, const float* __restrict__ gsrc,
                                          int bg, int tid) {
    int br = tid >> 3, c = tid & 7;
    const float4* s = (const float4*)(gsrc + (size_t)(bg * BC + br) * HID) + c * 8;
    float* d = dst + br * HID;
#pragma unroll
    for (int i = 0; i < 8; ++i) {
        float4 v = __ldcg(s + i);
        *(float4*)(d + swz(c * 8 + i) * 4) = v;
    }
}

__device__ __forceinline__ void pref_x(float4* xr, const float* __restrict__ x,
                                       int bg, int t, int tid) {
    int br = tid >> 3, c = tid & 7;
    const float4* s =
        (const float4*)(x + ((size_t)(bg * BC + br) * T_LEN + t) * HID) + c * 8;
#pragma unroll
    for (int i = 0; i < 8; ++i) xr[i] = __ldcg(s + i);
}

__device__ __forceinline__ void store_x(const float4* xr, float* sx, int tid) {
    int br = tid >> 3, c = tid & 7;
    float* d = sx + br * HID;
#pragma unroll
    for (int i = 0; i < 8; ++i) *(float4*)(d + swz(c * 8 + i) * 4) = xr[i];
}

// ---------------------------------------------------------------------------
// Register-blocked GEMM: 4 batch rows x 2 units x 3 gates over a 32-float
// K-slice. 20 LDS.128 per 96 ffma2.
// cell c = i*2 + j (i: batch 0..3, j: unit 0..1)
// ---------------------------------------------------------------------------
__device__ __forceinline__ void gemm_block(
    const float* __restrict__ pA, const float* __restrict__ pB,
    const float* __restrict__ pWx, const float* __restrict__ pWh,
    int ks, u64* aR, u64* aZ, u64* aNX, u64* aNH)
{
    const int koff = ks * 32;
#pragma unroll
    for (int kk = 0; kk < 8; ++kk) {
        const int off = koff + ((kk ^ ks) << 2);
        ull2 va[4], vb[4];
#pragma unroll
        for (int i = 0; i < 4; ++i) {
            va[i] = *(const ull2*)(pA + i * HID + off);
            vb[i] = *(const ull2*)(pB + i * HID + off);
        }
#pragma unroll
        for (int j = 0; j < 2; ++j) {
            const float* wx = pWx + j * HID;
            const float* wh = pWh + j * HID;
            ull2 rx = *(const ull2*)(wx + off);
            ull2 zx = *(const ull2*)(wx + 8 * HID + off);
            ull2 nx = *(const ull2*)(wx + 16 * HID + off);
            ull2 rh = *(const ull2*)(wh + off);
            ull2 zh = *(const ull2*)(wh + 8 * HID + off);
            ull2 nh = *(const ull2*)(wh + 16 * HID + off);
#pragma unroll
            for (int i = 0; i < 4; ++i) {
                const int c = i * 2 + j;
                ffma2(aR[c],  rx.x, va[i].x); ffma2(aR[c],  rx.y, va[i].y);
                ffma2(aR[c],  rh.x, vb[i].x); ffma2(aR[c],  rh.y, vb[i].y);
                ffma2(aZ[c],  zx.x, va[i].x); ffma2(aZ[c],  zx.y, va[i].y);
                ffma2(aZ[c],  zh.x, vb[i].x); ffma2(aZ[c],  zh.y, vb[i].y);
                ffma2(aNX[c], nx.x, va[i].x); ffma2(aNX[c], nx.y, va[i].y);
                ffma2(aNH[c], nh.x, vb[i].x); ffma2(aNH[c], nh.y, vb[i].y);
            }
        }
    }
}

// butterfly: reduce 8 cells over 8 ks-lanes; lane ks ends with cell ks's sum
__device__ __forceinline__ float red8(float* v, int ks) {
#pragma unroll
    for (int c = 0; c < 4; ++c) {
        float keep = (ks & 4) ? v[c + 4] : v[c];
        float send = (ks & 4) ? v[c]     : v[c + 4];
        v[c] = keep + __shfl_xor_sync(0xffffffffu, send, 4);
    }
#pragma unroll
    for (int c = 0; c < 2; ++c) {
        float keep = (ks & 2) ? v[c + 2] : v[c];
        float send = (ks & 2) ? v[c]     : v[c + 2];
        v[c] = keep + __shfl_xor_sync(0xffffffffu, send, 2);
    }
    float keep = (ks & 1) ? v[1] : v[0];
    float send = (ks & 1) ? v[0] : v[1];
    return keep + __shfl_xor_sync(0xffffffffu, send, 1);
}

__device__ __forceinline__ void finalize_store(
    u64* aR, u64* aZ, u64* aNX, u64* aNH,
    float br, float bz, float bxn, float bhn,
    const float* __restrict__ holdTile, float* __restrict__ gdst,
    int b4, int u2, int ks, int bg, int hg)
{
    float vR[8], vZ[8], vX[8], vH[8];
#pragma unroll
    for (int c = 0; c < 8; ++c) {
        vR[c] = us(aR[c]); vZ[c] = us(aZ[c]);
        vX[c] = us(aNX[c]); vH[c] = us(aNH[c]);
    }
    float R  = red8(vR, ks);
    float Z  = red8(vZ, ks);
    float X  = red8(vX, ks);
    float Hh = red8(vH, ks);

    int b_loc = b4 * 4 + (ks >> 1);
    int u_loc = u2 * 2 + (ks & 1);
    int e = hg * UC + u_loc;
    int g = e >> 2;
    float hold = holdTile[b_loc * HID + (swz(g) << 2) + (e & 3)];

    float r = sigm(R + br);
    float z = sigm(Z + bz);
    float n = tanh_(X + bxn + r * (Hh + bhn));
    float hn = z * hold + (1.0f - z) * n;
    gdst[(size_t)(bg * BC + b_loc) * HID + e] = hn;
}

// ---------------------------------------------------------------------------
__global__ void __launch_bounds__(NTHR, 1)
gru_persistent(const float* __restrict__ x,
               const float* __restrict__ Wx0, const float* __restrict__ bx0,
               const float* __restrict__ Wh0, const float* __restrict__ bh0,
               const float* __restrict__ Wx1, const float* __restrict__ bx1,
               const float* __restrict__ Wh1, const float* __restrict__ bh1,
               const float* __restrict__ Wo,  const float* __restrict__ bo,
               float* __restrict__ out)
{
    extern __shared__ float sm[];
    float* sWx0 = sm;
    float* sWh0 = sWx0 + WSZ;
    float* sWx1 = sWh0 + WSZ;
    float* sWh1 = sWx1 + WSZ;
    float* sx   = sWh1 + WSZ;
    float* sh0  = sx  + TSZ;
    float* sh1  = sh0 + TSZ;

    const int tid = threadIdx.x;
    const int bg  = blockIdx.x >> 5;
    const int hg  = blockIdx.x & 31;
    const int b4  = tid >> 5;            // warp: 4 batch rows b4*4..+3
    const int u2  = (tid >> 3) & 3;      // unit pair: u2*2, u2*2+1
    const int ks  = tid & 7;             // K-slice [ks*32, ks*32+32)

    fill_w(sWx0, Wx0, hg, tid);
    fill_w(sWh0, Wh0, hg, tid);
    fill_w(sWx1, Wx1, hg, tid);
    fill_w(sWh1, Wh1, hg, tid);
    for (int i = tid; i < TSZ; i += NTHR) { sh0[i] = 0.0f; sh1[i] = 0.0f; }
    {
        float4 xr[8];
        pref_x(xr, x, bg, 0, tid);
        store_x(xr, sx, tid);
    }
    __syncthreads();

    // biases for this thread's finalize unit
    const int ugf = hg * UC + u2 * 2 + (ks & 1);
    const float br0  = bx0[ugf] + bh0[ugf];
    const float bz0  = bx0[HID + ugf] + bh0[HID + ugf];
    const float bxn0 = bx0[2 * HID + ugf], bhn0 = bh0[2 * HID + ugf];
    const float br1  = bx1[ugf] + bh1[ugf];
    const float bz1  = bx1[HID + ugf] + bh1[HID + ugf];
    const float bxn1 = bx1[2 * HID + ugf], bhn1 = bh1[2 * HID + ugf];

    const float* pWx0 = sWx0 + (u2 * 2) * HID;
    const float* pWh0 = sWh0 + (u2 * 2) * HID;
    const float* pWx1 = sWx1 + (u2 * 2) * HID;
    const float* pWh1 = sWh1 + (u2 * 2) * HID;
    const int vbase = (b4 * 4) * HID;

    u64* myflag = &g_flag[bg * HGN + hg];
    const u64 base = ldacq(myflag);

    u64 aR[8], aZ[8], aNX[8], aNH[8];

    for (int t = 0; t < T_LEN; ++t) {
        // ================= phase A: layer 0 =================
#pragma unroll
        for (int c = 0; c < 8; ++c) { aR[c] = 0; aZ[c] = 0; aNX[c] = 0; aNH[c] = 0; }
        gemm_block(sx + vbase, sh0 + vbase, pWx0, pWh0, ks, aR, aZ, aNX, aNH);
        finalize_store(aR, aZ, aNX, aNH, br0, bz0, bxn0, bhn0,
                       sh0, g_h0, b4, u2, ks, bg, hg);
        __syncthreads();
        if (tid == 0) { __threadfence(); strel(myflag, base + (u64)(2 * t + 1)); }

        float4 xr[8];
        if (t + 1 < T_LEN) pref_x(xr, x, bg, t + 1, tid);   // overlap with spin

        if (tid < HGN) {
            const u64* f = &g_flag[bg * HGN + tid];
            while (ldacq(f) < base + (u64)(2 * t + 1)) __nanosleep(32);
        }
        __syncthreads();
        load_tile(sh0, g_h0, bg, tid);
        if (t + 1 < T_LEN) store_x(xr, sx, tid);
        __syncthreads();

        // ================= phase B: layer 1 =================
#pragma unroll
        for (int c = 0; c < 8; ++c) { aR[c] = 0; aZ[c] = 0; aNX[c] = 0; aNH[c] = 0; }
        gemm_block(sh0 + vbase, sh1 + vbase, pWx1, pWh1, ks, aR, aZ, aNX, aNH);
        finalize_store(aR, aZ, aNX, aNH, br1, bz1, bxn1, bhn1,
                       sh1, g_h1, b4, u2, ks, bg, hg);
        __syncthreads();
        if (tid == 0) { __threadfence(); strel(myflag, base + (u64)(2 * t + 2)); }

        if (tid < HGN) {
            const u64* f = &g_flag[bg * HGN + tid];
            while (ldacq(f) < base + (u64)(2 * t + 2)) __nanosleep(32);
        }
        __syncthreads();
        load_tile(sh1, g_h1, bg, tid);
        __syncthreads();
    }

    // ---- output projection: out = h1 @ Wo.T + bo (hg<16 covers 128 cols) ----
    if (hg < 16) {
        const int b = tid >> 3, o8 = tid & 7;
        const int o = hg * 8 + o8;
        const float* ph = sh1 + b * HID;
        const ull2* wo = (const ull2*)(Wo + (size_t)o * HID);
        u64 a0 = 0, a1 = 0;
#pragma unroll 8
        for (int g = 0; g < 64; ++g) {
            ull2 hv = *(const ull2*)(ph + swz(g) * 4);
            ull2 wv = wo[g];
            ffma2(a0, wv.x, hv.x);
            ffma2(a1, wv.y, hv.y);
        }
        out[(size_t)(bg * BC + b) * 128 + o] = us(a0) + us(a1) + __ldg(bo + o);
    }
}

// ---------------------------------------------------------------------------
extern "C" void kernel_launch(void* const* d_in, const int* in_sizes, int n_in,
                              void* d_out, int out_size) {
    (void)in_sizes; (void)n_in; (void)out_size;
    const float* x   = (const float*)d_in[0];
    const float* Wx0 = (const float*)d_in[1];
    const float* bx0 = (const float*)d_in[2];
    const float* Wh0 = (const float*)d_in[3];
    const float* bh0 = (const float*)d_in[4];
    const float* Wx1 = (const float*)d_in[5];
    const float* bx1 = (const float*)d_in[6];
    const float* Wh1 = (const float*)d_in[7];
    const float* bh1 = (const float*)d_in[8];
    const float* Wo  = (const float*)d_in[9];
    const float* bo  = (const float*)d_in[10];
    float* out = (float*)d_out;

    cudaFuncSetAttribute(gru_persistent,
                         cudaFuncAttributeMaxDynamicSharedMemorySize, SMEM_BYTES);
    gru_persistent<<<BGN * HGN, NTHR, SMEM_BYTES>>>(
        x, Wx0, bx0, Wh0, bh0, Wx1, bx1, Wh1, bh1, Wo, bo, out);
}